// round 10
// baseline (speedup 1.0000x reference)
#include <cuda_runtime.h>
#include <cuda_bf16.h>
#include <cstdint>
#include <cstddef>

typedef unsigned long long ull;
typedef unsigned int u32;

#define BB 32
#define TT 1024
#define HH 512
#define GG 2048
#define NCTA 128            // lstm CTAs

// ---------------- device scratch (allocations are forbidden) ----------------
__device__ __align__(16) float g_xp[(size_t)TT * GG * BB];   // x_proj[t][g][b]
// fragment-major packed h image: [phase][block(kw,kt,nt)][lane][j], 64KB/phase
__device__ __align__(16) u32 g_himg[2][16384];
__device__ __align__(128) unsigned g_flags[NCTA * 8];

// ---------------- helpers ----------------
__device__ __forceinline__ ull fadd2(ull a, ull b) {
    ull d; asm("add.rn.f32x2 %0, %1, %2;" : "=l"(d) : "l"(a), "l"(b)); return d;
}
__device__ __forceinline__ ull pack2(float x, float y) {
    ull d; asm("mov.b64 %0, {%1, %2};" : "=l"(d) : "f"(x), "f"(y)); return d;
}
__device__ __forceinline__ float sigm(float x) { return __fdividef(1.0f, 1.0f + __expf(-x)); }
__device__ __forceinline__ float tanh_(float x) { return 1.0f - __fdividef(2.0f, __expf(2.0f * x) + 1.0f); }

__device__ __forceinline__ u32 pack_bf2(float a, float b) {
    return (u32)__bfloat16_as_ushort(__float2bfloat16(a))
         | ((u32)__bfloat16_as_ushort(__float2bfloat16(b)) << 16);
}
__device__ __forceinline__ void mma16816(float& c0, float& c1, float& c2, float& c3,
                                         u32 a0, u32 a1, u32 a2, u32 a3, u32 b0, u32 b1) {
    asm volatile(
        "mma.sync.aligned.m16n8k16.row.col.f32.bf16.bf16.f32 "
        "{%0,%1,%2,%3}, {%4,%5,%6,%7}, {%8,%9}, {%0,%1,%2,%3};"
        : "+f"(c0), "+f"(c1), "+f"(c2), "+f"(c3)
        : "r"(a0), "r"(a1), "r"(a2), "r"(a3), "r"(b0), "r"(b1));
}

// =========================================================================
// Kernel 1: HMMA x_proj (R7-proven). grid (16, 256). Early-exit past maxlen.
// =========================================================================
#define APITCH 36
#define PLW (128 * APITCH)

__global__ __launch_bounds__(256, 1) void xproj_kernel(
    const float* __restrict__ src, const float* __restrict__ Wih,
    const float* __restrict__ bih, const float* __restrict__ bhh,
    const int* __restrict__ lengths)
{
    extern __shared__ u32 smw[];
    u32* Ah = smw;
    u32* Al = smw + PLW;
    u32* Bh = smw + 2 * PLW;
    u32* Bl = smw + 3 * PLW;

    const int tid = threadIdx.x;
    if (blockIdx.x == 0 && blockIdx.y == 0) {
        uint4 z = {0, 0, 0, 0};
        for (int i = tid; i < 2 * 16384 / 4; i += 256) ((uint4*)g_himg)[i] = z;
        for (int i = tid; i < NCTA * 8; i += 256) g_flags[i] = 0u;
    }

    const int n0 = blockIdx.y * 128;
    if ((n0 >> 5) >= lengths[0]) return;         // whole n-tile past maxlen
    const int g0 = blockIdx.x * 128;
    const int warp = tid >> 5, lane = tid & 31;
    const int wm = warp & 3, wn = warp >> 2;
    const int g_ = lane >> 2, t_ = lane & 3;

    float C[2][8][4];
#pragma unroll
    for (int mt = 0; mt < 2; mt++)
#pragma unroll
        for (int nt = 0; nt < 8; nt++)
#pragma unroll
            for (int r = 0; r < 4; r++) C[mt][nt][r] = 0.0f;

    for (int kc = 0; kc < 8; kc++) {
        const int c0 = kc * 64;
#pragma unroll
        for (int i = 0; i < 8; i++) {
            int idx = tid + i * 256;
            int row = idx >> 4, cq = idx & 15;
            float4 w = *(const float4*)(Wih + (size_t)(g0 + row) * HH + c0 + cq * 4);
            float hx = __bfloat162float(__float2bfloat16(w.x));
            float hy = __bfloat162float(__float2bfloat16(w.y));
            float hz = __bfloat162float(__float2bfloat16(w.z));
            float hw = __bfloat162float(__float2bfloat16(w.w));
            *(uint2*)(Ah + row * APITCH + cq * 2) =
                make_uint2(pack_bf2(w.x, w.y), pack_bf2(w.z, w.w));
            *(uint2*)(Al + row * APITCH + cq * 2) =
                make_uint2(pack_bf2(w.x - hx, w.y - hy), pack_bf2(w.z - hz, w.w - hw));
        }
#pragma unroll
        for (int i = 0; i < 8; i++) {
            int idx = tid + i * 256;
            int n = idx >> 4, cq = idx & 15;
            int N = n0 + n, b = N & 31, tt = N >> 5;
            float4 w = *(const float4*)(src + ((size_t)b * TT + tt) * HH + c0 + cq * 4);
            float hx = __bfloat162float(__float2bfloat16(w.x));
            float hy = __bfloat162float(__float2bfloat16(w.y));
            float hz = __bfloat162float(__float2bfloat16(w.z));
            float hw = __bfloat162float(__float2bfloat16(w.w));
            *(uint2*)(Bh + n * APITCH + cq * 2) =
                make_uint2(pack_bf2(w.x, w.y), pack_bf2(w.z, w.w));
            *(uint2*)(Bl + n * APITCH + cq * 2) =
                make_uint2(pack_bf2(w.x - hx, w.y - hy), pack_bf2(w.z - hz, w.w - hw));
        }
        __syncthreads();

#pragma unroll
        for (int kt = 0; kt < 4; kt++) {
            const int wbase = kt * 8 + t_;
            u32 ah[2][4], al[2][4];
#pragma unroll
            for (int mt = 0; mt < 2; mt++) {
                int ra = wm * 32 + mt * 16 + g_;
                ah[mt][0] = Ah[ra * APITCH + wbase];
                ah[mt][1] = Ah[(ra + 8) * APITCH + wbase];
                ah[mt][2] = Ah[ra * APITCH + wbase + 4];
                ah[mt][3] = Ah[(ra + 8) * APITCH + wbase + 4];
                al[mt][0] = Al[ra * APITCH + wbase];
                al[mt][1] = Al[(ra + 8) * APITCH + wbase];
                al[mt][2] = Al[ra * APITCH + wbase + 4];
                al[mt][3] = Al[(ra + 8) * APITCH + wbase + 4];
            }
#pragma unroll
            for (int nt = 0; nt < 8; nt++) {
                int nc = wn * 64 + nt * 8 + g_;
                u32 b0h = Bh[nc * APITCH + wbase];
                u32 b1h = Bh[nc * APITCH + wbase + 4];
                u32 b0l = Bl[nc * APITCH + wbase];
                u32 b1l = Bl[nc * APITCH + wbase + 4];
#pragma unroll
                for (int mt = 0; mt < 2; mt++) {
                    mma16816(C[mt][nt][0], C[mt][nt][1], C[mt][nt][2], C[mt][nt][3],
                             ah[mt][0], ah[mt][1], ah[mt][2], ah[mt][3], b0h, b1h);
                    mma16816(C[mt][nt][0], C[mt][nt][1], C[mt][nt][2], C[mt][nt][3],
                             al[mt][0], al[mt][1], al[mt][2], al[mt][3], b0h, b1h);
                    mma16816(C[mt][nt][0], C[mt][nt][1], C[mt][nt][2], C[mt][nt][3],
                             ah[mt][0], ah[mt][1], ah[mt][2], ah[mt][3], b0l, b1l);
                }
            }
        }
        __syncthreads();
    }

#pragma unroll
    for (int mt = 0; mt < 2; mt++) {
        int r0 = g0 + wm * 32 + mt * 16 + g_;
        int r1 = r0 + 8;
        float bs0 = bih[r0] + bhh[r0];
        float bs1 = bih[r1] + bhh[r1];
        ull bias0 = pack2(bs0, bs0), bias1 = pack2(bs1, bs1);
#pragma unroll
        for (int nt = 0; nt < 8; nt++) {
            int N = n0 + wn * 64 + nt * 8 + 2 * t_;
            int tt = N >> 5, b = N & 31;
            *(ull*)(g_xp + ((size_t)tt * GG + r0) * BB + b)
                = fadd2(pack2(C[mt][nt][0], C[mt][nt][1]), bias0);
            *(ull*)(g_xp + ((size_t)tt * GG + r1) * BB + b)
                = fadd2(pack2(C[mt][nt][2], C[mt][nt][3]), bias1);
        }
    }
}

// =========================================================================
// Kernel 2: HMMA recurrence, fragment-major direct-L2 B loads (no smem stage).
// =========================================================================
__global__ __launch_bounds__(256, 1) void lstm_kernel(
    const int* __restrict__ lengths, const float* __restrict__ Whh,
    float* __restrict__ out)
{
    __shared__ float red_s[8 * 16 * 40];     // red[kw][m][40]

    const int tid  = threadIdx.x;
    const int cta  = blockIdx.x;
    const int kw   = tid >> 5;               // warp = K chunk [kw*64, +64)
    const int lane = tid & 31;
    const int g_   = lane >> 2;
    const int t_   = lane & 3;
    const int len0 = lengths[0];             // max length (sorted desc)

    // ---- prologue: W fragments (hi, lo), rows m = gate*4 + unit
    u32 Ahi[4][4], Alo[4][4];
    {
        const float* p0 = Whh + (size_t)((g_ >> 2) * HH + cta * 4 + (g_ & 3)) * HH;
        const float* p1 = p0 + (size_t)2 * HH * HH;   // rows +8 => gates 2,3
#pragma unroll
        for (int kt = 0; kt < 4; kt++) {
            int k0 = kw * 64 + kt * 16 + 2 * t_;
            float2 vv[4] = { *(const float2*)(p0 + k0), *(const float2*)(p1 + k0),
                             *(const float2*)(p0 + k0 + 8), *(const float2*)(p1 + k0 + 8) };
#pragma unroll
            for (int r = 0; r < 4; r++) {
                float hx = __bfloat162float(__float2bfloat16(vv[r].x));
                float hy = __bfloat162float(__float2bfloat16(vv[r].y));
                Ahi[kt][r] = pack_bf2(vv[r].x, vv[r].y);
                Alo[kt][r] = pack_bf2(vv[r].x - hx, vv[r].y - hy);
            }
        }
    }

    // updater mapping (tid < 128): ub = batch, uu = unit
    const int ub = tid >> 2, uu = tid & 3;
    int   len = 0;
    float c_r = 0.0f, h_r = 0.0f;
    if (tid < 128) len = lengths[ub];

    // precompute fragment-major publish index for this updater's h word
    int widx = 0;
    {
        int k = cta * 4 + uu;
        int pkw = k >> 6, klo = k & 63, pkt = klo >> 4, r = klo & 15;
        int pt, pj;
        if (r < 8) { pt = r >> 1; pj = r & 1; }
        else       { pt = (r - 8) >> 1; pj = 2 + (r & 1); }
        int pnt = ub >> 3, pg = ub & 7;
        widx = (pkw * 16 + pkt * 4 + pnt) * 128 + (pg * 4 + pt) * 4 + pj;
    }

    const int ldbase = kw * 2048 + lane * 4;   // words

    for (int t = 0; t < len0; t++) {
        const int p = t & 1;

        // xg prefetch (in flight during poll)
        float xg0 = 0.f, xg1 = 0.f, xg2 = 0.f, xg3 = 0.f;
        if (tid < 128) {
            const float* xp = g_xp + ((size_t)t * GG + cta * 4 + uu) * BB + ub;
            xg0 = xp[0 * HH * BB];
            xg1 = xp[1 * HH * BB];
            xg2 = xp[2 * HH * BB];
            xg3 = xp[3 * HH * BB];
        }

        // grid barrier: all 128 CTAs published step t-1 (also gates publish safety)
        if (t > 0 && tid < NCTA) {
            const unsigned* f = &g_flags[tid * 8];
            unsigned v;
            do {
                asm volatile("ld.acquire.gpu.u32 %0, [%1];" : "=r"(v) : "l"(f) : "memory");
            } while (v < (unsigned)t);
        }
        __syncthreads();

        // ---- direct fragment loads: 16 coalesced uint4 ldcg per lane
        const u32* img = g_himg[p];
        uint4 u[16];
#pragma unroll
        for (int i = 0; i < 16; i++)
            u[i] = __ldcg((const uint4*)(img + ldbase + i * 128));

        // ---- merged 3-term MMA
        float C[4][4];
#pragma unroll
        for (int nt = 0; nt < 4; nt++)
#pragma unroll
            for (int r = 0; r < 4; r++) C[nt][r] = 0.0f;

#pragma unroll
        for (int kt = 0; kt < 4; kt++) {
#pragma unroll
            for (int nt = 0; nt < 4; nt++) {
                uint4 w = u[kt * 4 + nt];
                u32 b0h = __byte_perm(w.x, w.y, 0x5410);
                u32 b1h = __byte_perm(w.z, w.w, 0x5410);
                u32 b0l = __byte_perm(w.x, w.y, 0x7632);
                u32 b1l = __byte_perm(w.z, w.w, 0x7632);
                mma16816(C[nt][0], C[nt][1], C[nt][2], C[nt][3],
                         Ahi[kt][0], Ahi[kt][1], Ahi[kt][2], Ahi[kt][3], b0h, b1h);
                mma16816(C[nt][0], C[nt][1], C[nt][2], C[nt][3],
                         Alo[kt][0], Alo[kt][1], Alo[kt][2], Alo[kt][3], b0h, b1h);
                mma16816(C[nt][0], C[nt][1], C[nt][2], C[nt][3],
                         Ahi[kt][0], Ahi[kt][1], Ahi[kt][2], Ahi[kt][3], b0l, b1l);
            }
        }

        // write k-partials: red[kw][m][40]
        {
            float* rw = red_s + kw * 16 * 40;
#pragma unroll
            for (int nt = 0; nt < 4; nt++) {
                int n = nt * 8 + 2 * t_;
                *(float2*)(rw + g_ * 40 + n)       = make_float2(C[nt][0], C[nt][1]);
                *(float2*)(rw + (g_ + 8) * 40 + n) = make_float2(C[nt][2], C[nt][3]);
            }
        }
        __syncthreads();

        // updaters: reduce 8 k-partials, gates, state, fragment-major publish
        if (tid < 128) {
            float s[4];
#pragma unroll
            for (int gt = 0; gt < 4; gt++) {
                int m = gt * 4 + uu;
                float a0 = 0.f, a1 = 0.f;
#pragma unroll
                for (int w = 0; w < 8; w += 2) {
                    a0 += red_s[(w * 16 + m) * 40 + ub];
                    a1 += red_s[((w + 1) * 16 + m) * 40 + ub];
                }
                s[gt] = a0 + a1;
            }
            float gi_ = sigm(xg0 + s[0]);
            float gf  = sigm(xg1 + s[1]);
            float gg  = tanh_(xg2 + s[2]);
            float go  = sigm(xg3 + s[3]);
            float cn = gf * c_r + gi_ * gg;
            float hn = go * tanh_(cn);
            bool valid = (t < len);
            if (valid) { c_r = cn; h_r = hn; }
            float out_val = valid ? hn : 0.0f;

            // packed (hi, lo) publish: ONE 4B store at precomputed index
            __nv_bfloat16 hh = __float2bfloat16(h_r);
            float rlo = h_r - __bfloat162float(hh);
            u32 word = (u32)__bfloat16_as_ushort(hh)
                     | ((u32)__bfloat16_as_ushort(__float2bfloat16(rlo)) << 16);
            g_himg[1 - p][widx] = word;

            // updater-warps-only barrier, then release (MMA warps not held)
            asm volatile("bar.sync 1, 128;" ::: "memory");
            if (tid == 0) {
                asm volatile("st.release.gpu.u32 [%0], %1;"
                             :: "l"(&g_flags[cta * 8]), "r"((unsigned)(t + 1)) : "memory");
            }
            out[((size_t)t * BB + ub) * HH + cta * 4 + uu] = out_val;
        }
    }

    // zero the out tail (t >= maxlen): pad region of pad_packed output
    for (int t = len0 + (tid >> 7); t < TT; t += 2) {
        int r = tid & 127;
        out[((size_t)t * BB + (r >> 2)) * HH + cta * 4 + (r & 3)] = 0.0f;
    }

    // final hT, cT
    if (tid < 128) {
        size_t base = (size_t)TT * BB * HH;
        out[base + (size_t)ub * HH + cta * 4 + uu] = h_r;
        out[base + (size_t)BB * HH + (size_t)ub * HH + cta * 4 + uu] = c_r;
    }
}

// =========================================================================
extern "C" void kernel_launch(void* const* d_in, const int* in_sizes, int n_in,
                              void* d_out, int out_size) {
    const float* src  = (const float*)d_in[0];
    const int*   lens = (const int*)d_in[1];
    const float* Wih  = (const float*)d_in[2];
    const float* Whh  = (const float*)d_in[3];
    const float* bih  = (const float*)d_in[4];
    const float* bhh  = (const float*)d_in[5];
    float* out = (float*)d_out;

    const int smem_xproj = 4 * PLW * 4;          // 73,728 B
    cudaFuncSetAttribute(xproj_kernel, cudaFuncAttributeMaxDynamicSharedMemorySize, smem_xproj);

    dim3 grid(16, 256);
    xproj_kernel<<<grid, 256, smem_xproj>>>(src, Wih, bih, bhh, lens);
    lstm_kernel<<<NCTA, 256>>>(lens, Whh, out);
}

// round 11
// speedup vs baseline: 1.6105x; 1.6105x over previous
#include <cuda_runtime.h>
#include <cuda_fp16.h>
#include <cstdint>
#include <cstddef>

typedef unsigned long long ull;
typedef unsigned int u32;

#define BB 32
#define TT 1024
#define HH 512
#define GG 2048
#define NCTA 128            // lstm CTAs
#define PKP 260             // h image pitch in u32 words (256 data + 4 pad)
#define IMG_B (32 * PKP * 4)    // 33280 bytes per phase

// ---------------- device scratch (allocations are forbidden) ----------------
__device__ __align__(16) float g_xp[(size_t)TT * GG * BB];   // x_proj[t][g][b]
__device__ __align__(16) u32 g_hpk[2][32 * PKP];             // fp16x2 h image [b][k/2]
__device__ __align__(128) unsigned g_flags[NCTA * 8];

// ---------------- helpers ----------------
__device__ __forceinline__ ull fadd2(ull a, ull b) {
    ull d; asm("add.rn.f32x2 %0, %1, %2;" : "=l"(d) : "l"(a), "l"(b)); return d;
}
__device__ __forceinline__ ull pack2(float x, float y) {
    ull d; asm("mov.b64 %0, {%1, %2};" : "=l"(d) : "f"(x), "f"(y)); return d;
}
__device__ __forceinline__ float sigm(float x) { return __fdividef(1.0f, 1.0f + __expf(-x)); }
__device__ __forceinline__ float tanh_(float x) { return 1.0f - __fdividef(2.0f, __expf(2.0f * x) + 1.0f); }

__device__ __forceinline__ u32 smem_u32(const void* p) {
    u32 a; asm("{ .reg .u64 t; cvta.to.shared.u64 t, %1; cvt.u32.u64 %0, t; }" : "=r"(a) : "l"(p)); return a;
}
__device__ __forceinline__ void cp_async16(u32 dst, const void* src) {
    asm volatile("cp.async.cg.shared.global [%0], [%1], 16;" :: "r"(dst), "l"(src));
}
__device__ __forceinline__ u32 pack_hf2(float a, float b) {
    return (u32)__half_as_ushort(__float2half_rn(a))
         | ((u32)__half_as_ushort(__float2half_rn(b)) << 16);
}
// fp16 mma m16n8k16, f32 accum (baseline sm_80)
__device__ __forceinline__ void mma16816h(float& c0, float& c1, float& c2, float& c3,
                                          u32 a0, u32 a1, u32 a2, u32 a3, u32 b0, u32 b1) {
    asm volatile(
        "mma.sync.aligned.m16n8k16.row.col.f32.f16.f16.f32 "
        "{%0,%1,%2,%3}, {%4,%5,%6,%7}, {%8,%9}, {%0,%1,%2,%3};"
        : "+f"(c0), "+f"(c1), "+f"(c2), "+f"(c3)
        : "r"(a0), "r"(a1), "r"(a2), "r"(a3), "r"(b0), "r"(b1));
}

// =========================================================================
// Kernel 1: HMMA x_proj, fp16 2-term (A = W hi+lo, B = src single plane).
// grid (16, 256): 128 g x 128 n per CTA. Early-exit past maxlen.
// =========================================================================
#define APITCH 36
#define PLW (128 * APITCH)

__global__ __launch_bounds__(256, 1) void xproj_kernel(
    const float* __restrict__ src, const float* __restrict__ Wih,
    const float* __restrict__ bih, const float* __restrict__ bhh,
    const int* __restrict__ lengths)
{
    extern __shared__ u32 smw[];
    u32* Ah = smw;
    u32* Al = smw + PLW;
    u32* Bh = smw + 2 * PLW;

    const int tid = threadIdx.x;
    if (blockIdx.x == 0 && blockIdx.y == 0) {
        uint4 z = {0, 0, 0, 0};
        const int n16 = (int)(sizeof(g_hpk) / 16);
        for (int i = tid; i < n16; i += 256) ((uint4*)g_hpk)[i] = z;
        for (int i = tid; i < NCTA * 8; i += 256) g_flags[i] = 0u;
    }

    const int n0 = blockIdx.y * 128;
    if ((n0 >> 5) >= lengths[0]) return;         // whole n-tile past maxlen
    const int g0 = blockIdx.x * 128;
    const int warp = tid >> 5, lane = tid & 31;
    const int wm = warp & 3, wn = warp >> 2;
    const int g_ = lane >> 2, t_ = lane & 3;

    float C[2][8][4];
#pragma unroll
    for (int mt = 0; mt < 2; mt++)
#pragma unroll
        for (int nt = 0; nt < 8; nt++)
#pragma unroll
            for (int r = 0; r < 4; r++) C[mt][nt][r] = 0.0f;

    for (int kc = 0; kc < 8; kc++) {
        const int c0 = kc * 64;
        // stage A = W rows [g0,g0+128) cols [c0,c0+64): hi + lo fp16 planes
#pragma unroll
        for (int i = 0; i < 8; i++) {
            int idx = tid + i * 256;
            int row = idx >> 4, cq = idx & 15;
            float4 w = *(const float4*)(Wih + (size_t)(g0 + row) * HH + c0 + cq * 4);
            float hx = __half2float(__float2half_rn(w.x));
            float hy = __half2float(__float2half_rn(w.y));
            float hz = __half2float(__float2half_rn(w.z));
            float hw = __half2float(__float2half_rn(w.w));
            *(uint2*)(Ah + row * APITCH + cq * 2) =
                make_uint2(pack_hf2(w.x, w.y), pack_hf2(w.z, w.w));
            *(uint2*)(Al + row * APITCH + cq * 2) =
                make_uint2(pack_hf2(w.x - hx, w.y - hy), pack_hf2(w.z - hz, w.w - hw));
        }
        // stage B = src, single fp16 plane
#pragma unroll
        for (int i = 0; i < 8; i++) {
            int idx = tid + i * 256;
            int n = idx >> 4, cq = idx & 15;
            int N = n0 + n, b = N & 31, tt = N >> 5;
            float4 w = *(const float4*)(src + ((size_t)b * TT + tt) * HH + c0 + cq * 4);
            *(uint2*)(Bh + n * APITCH + cq * 2) =
                make_uint2(pack_hf2(w.x, w.y), pack_hf2(w.z, w.w));
        }
        __syncthreads();

#pragma unroll
        for (int kt = 0; kt < 4; kt++) {
            const int wbase = kt * 8 + t_;
            u32 ah[2][4], al[2][4];
#pragma unroll
            for (int mt = 0; mt < 2; mt++) {
                int ra = wm * 32 + mt * 16 + g_;
                ah[mt][0] = Ah[ra * APITCH + wbase];
                ah[mt][1] = Ah[(ra + 8) * APITCH + wbase];
                ah[mt][2] = Ah[ra * APITCH + wbase + 4];
                ah[mt][3] = Ah[(ra + 8) * APITCH + wbase + 4];
                al[mt][0] = Al[ra * APITCH + wbase];
                al[mt][1] = Al[(ra + 8) * APITCH + wbase];
                al[mt][2] = Al[ra * APITCH + wbase + 4];
                al[mt][3] = Al[(ra + 8) * APITCH + wbase + 4];
            }
#pragma unroll
            for (int nt = 0; nt < 8; nt++) {
                int nc = wn * 64 + nt * 8 + g_;
                u32 b0 = Bh[nc * APITCH + wbase];
                u32 b1 = Bh[nc * APITCH + wbase + 4];
#pragma unroll
                for (int mt = 0; mt < 2; mt++) {
                    mma16816h(C[mt][nt][0], C[mt][nt][1], C[mt][nt][2], C[mt][nt][3],
                              ah[mt][0], ah[mt][1], ah[mt][2], ah[mt][3], b0, b1);
                    mma16816h(C[mt][nt][0], C[mt][nt][1], C[mt][nt][2], C[mt][nt][3],
                              al[mt][0], al[mt][1], al[mt][2], al[mt][3], b0, b1);
                }
            }
        }
        __syncthreads();
    }

    // epilogue: + (b_ih + b_hh), store pairs to g_xp[t][g][b]
#pragma unroll
    for (int mt = 0; mt < 2; mt++) {
        int r0 = g0 + wm * 32 + mt * 16 + g_;
        int r1 = r0 + 8;
        float bs0 = bih[r0] + bhh[r0];
        float bs1 = bih[r1] + bhh[r1];
        ull bias0 = pack2(bs0, bs0), bias1 = pack2(bs1, bs1);
#pragma unroll
        for (int nt = 0; nt < 8; nt++) {
            int N = n0 + wn * 64 + nt * 8 + 2 * t_;
            int tt = N >> 5, b = N & 31;
            *(ull*)(g_xp + ((size_t)tt * GG + r0) * BB + b)
                = fadd2(pack2(C[mt][nt][0], C[mt][nt][1]), bias0);
            *(ull*)(g_xp + ((size_t)tt * GG + r1) * BB + b)
                = fadd2(pack2(C[mt][nt][2], C[mt][nt][3]), bias1);
        }
    }
}

// =========================================================================
// Kernel 2: fp16 2-term HMMA recurrence, 128 CTAs x 256 thr, M=16.
// h image: single fp16 plane (33 KB), cp.async staged (R7-proven transport).
// smem: [0:33280) image, [33280: +20480) reduction buffer.
// =========================================================================
#define SM_RED  IMG_B
#define SM_TOT_L (SM_RED + 8 * 16 * 40 * 4)     // 53,760 B

__global__ __launch_bounds__(256, 1) void lstm_kernel(
    const int* __restrict__ lengths, const float* __restrict__ Whh,
    float* __restrict__ out)
{
    extern __shared__ char smc[];
    const u32 sb = smem_u32(smc);
    const u32* pk = (const u32*)smc;
    float* red_s = (float*)(smc + SM_RED);

    const int tid  = threadIdx.x;
    const int cta  = blockIdx.x;
    const int kw   = tid >> 5;               // warp = K chunk [kw*64, +64)
    const int lane = tid & 31;
    const int g_   = lane >> 2;
    const int t_   = lane & 3;
    const int len0 = lengths[0];             // max length (sorted desc)

    // ---- prologue: W fragments (hi, lo fp16), rows m = gate*4 + unit
    u32 Ahi[4][4], Alo[4][4];
    {
        const float* p0 = Whh + (size_t)((g_ >> 2) * HH + cta * 4 + (g_ & 3)) * HH;
        const float* p1 = p0 + (size_t)2 * HH * HH;   // rows +8 => gates 2,3
#pragma unroll
        for (int kt = 0; kt < 4; kt++) {
            int k0 = kw * 64 + kt * 16 + 2 * t_;
            float2 vv[4] = { *(const float2*)(p0 + k0), *(const float2*)(p1 + k0),
                             *(const float2*)(p0 + k0 + 8), *(const float2*)(p1 + k0 + 8) };
#pragma unroll
            for (int r = 0; r < 4; r++) {
                float hx = __half2float(__float2half_rn(vv[r].x));
                float hy = __half2float(__float2half_rn(vv[r].y));
                Ahi[kt][r] = pack_hf2(vv[r].x, vv[r].y);
                Alo[kt][r] = pack_hf2(vv[r].x - hx, vv[r].y - hy);
            }
        }
    }

    // updater mapping (tid < 128): ub = batch, uu = unit
    const int ub = tid >> 2, uu = tid & 3;
    int   len = 0;
    float c_r = 0.0f, h_r = 0.0f;
    if (tid < 128) len = lengths[ub];
    const int pub_word = ub * PKP + cta * 2 + (uu >> 1);   // u32 index (pair of units)

    for (int t = 0; t < len0; t++) {
        const int p = t & 1;

        // xg prefetch (in flight during poll)
        float xg0 = 0.f, xg1 = 0.f, xg2 = 0.f, xg3 = 0.f;
        if (tid < 128) {
            const float* xp = g_xp + ((size_t)t * GG + cta * 4 + uu) * BB + ub;
            xg0 = xp[0 * HH * BB];
            xg1 = xp[1 * HH * BB];
            xg2 = xp[2 * HH * BB];
            xg3 = xp[3 * HH * BB];
        }

        // grid barrier: all 128 CTAs published step t-1
        if (t > 0 && tid < NCTA) {
            const unsigned* f = &g_flags[tid * 8];
            unsigned v;
            do {
                asm volatile("ld.acquire.gpu.u32 %0, [%1];" : "=r"(v) : "l"(f) : "memory");
            } while (v < (unsigned)t);
        }
        __syncthreads();

        // stage h image (33 KB, single plane, one wait)
        const u32* hsrc = g_hpk[p];
#pragma unroll
        for (int i = 0; i < 9; i++) {
            int idx = tid + i * 256;
            if (idx < (32 * PKP) / 4)
                cp_async16(sb + idx * 16, hsrc + idx * 4);
        }
        asm volatile("cp.async.commit_group;\ncp.async.wait_group 0;" ::: "memory");
        __syncthreads();

        // ---- 2-term MMA: 32 mma per warp
        float C[4][4];
#pragma unroll
        for (int nt = 0; nt < 4; nt++)
#pragma unroll
            for (int r = 0; r < 4; r++) C[nt][r] = 0.0f;

#pragma unroll
        for (int kt = 0; kt < 4; kt++) {
            const int wbase = kw * 32 + kt * 8 + t_;
#pragma unroll
            for (int nt = 0; nt < 4; nt++) {
                const int n = nt * 8 + g_;
                u32 b0 = pk[n * PKP + wbase];
                u32 b1 = pk[n * PKP + wbase + 4];
                mma16816h(C[nt][0], C[nt][1], C[nt][2], C[nt][3],
                          Ahi[kt][0], Ahi[kt][1], Ahi[kt][2], Ahi[kt][3], b0, b1);
                mma16816h(C[nt][0], C[nt][1], C[nt][2], C[nt][3],
                          Alo[kt][0], Alo[kt][1], Alo[kt][2], Alo[kt][3], b0, b1);
            }
        }

        // write k-partials: red[kw][m][40]
        {
            float* rw = red_s + kw * 16 * 40;
#pragma unroll
            for (int nt = 0; nt < 4; nt++) {
                int n = nt * 8 + 2 * t_;
                *(float2*)(rw + g_ * 40 + n)       = make_float2(C[nt][0], C[nt][1]);
                *(float2*)(rw + (g_ + 8) * 40 + n) = make_float2(C[nt][2], C[nt][3]);
            }
        }
        __syncthreads();

        // updaters: reduce 8 k-partials, gates, state, paired fp16 publish
        if (tid < 128) {
            float s[4];
#pragma unroll
            for (int gt = 0; gt < 4; gt++) {
                int m = gt * 4 + uu;
                float a0 = 0.f, a1 = 0.f;
#pragma unroll
                for (int w = 0; w < 8; w += 2) {
                    a0 += red_s[(w * 16 + m) * 40 + ub];
                    a1 += red_s[((w + 1) * 16 + m) * 40 + ub];
                }
                s[gt] = a0 + a1;
            }
            float gi_ = sigm(xg0 + s[0]);
            float gf  = sigm(xg1 + s[1]);
            float gg  = tanh_(xg2 + s[2]);
            float go  = sigm(xg3 + s[3]);
            float cn = gf * c_r + gi_ * gg;
            float hn = go * tanh_(cn);
            bool valid = (t < len);
            if (valid) { c_r = cn; h_r = hn; }
            float out_val = valid ? hn : 0.0f;

            // fp16 publish: pair units via shuffle, even-uu lane stores one u32
            u32 hb = (u32)__half_as_ushort(__float2half_rn(h_r));
            u32 pb = __shfl_down_sync(0xFFFFFFFFu, hb, 1);
            if ((uu & 1) == 0)
                g_hpk[1 - p][pub_word] = hb | (pb << 16);

            // updater-warps-only barrier, then release (MMA warps not held)
            asm volatile("bar.sync 1, 128;" ::: "memory");
            if (tid == 0) {
                asm volatile("st.release.gpu.u32 [%0], %1;"
                             :: "l"(&g_flags[cta * 8]), "r"((unsigned)(t + 1)) : "memory");
            }
            out[((size_t)t * BB + ub) * HH + cta * 4 + uu] = out_val;
        }
    }

    // zero the out tail (t >= maxlen): pad region of pad_packed output
    for (int t = len0 + (tid >> 7); t < TT; t += 2) {
        int r = tid & 127;
        out[((size_t)t * BB + (r >> 2)) * HH + cta * 4 + (r & 3)] = 0.0f;
    }

    // final hT, cT
    if (tid < 128) {
        size_t base = (size_t)TT * BB * HH;
        out[base + (size_t)ub * HH + cta * 4 + uu] = h_r;
        out[base + (size_t)BB * HH + (size_t)ub * HH + cta * 4 + uu] = c_r;
    }
}

// =========================================================================
extern "C" void kernel_launch(void* const* d_in, const int* in_sizes, int n_in,
                              void* d_out, int out_size) {
    const float* src  = (const float*)d_in[0];
    const int*   lens = (const int*)d_in[1];
    const float* Wih  = (const float*)d_in[2];
    const float* Whh  = (const float*)d_in[3];
    const float* bih  = (const float*)d_in[4];
    const float* bhh  = (const float*)d_in[5];
    float* out = (float*)d_out;

    const int smem_xproj = 3 * PLW * 4;          // 55,296 B
    cudaFuncSetAttribute(xproj_kernel, cudaFuncAttributeMaxDynamicSharedMemorySize, smem_xproj);
    cudaFuncSetAttribute(lstm_kernel,  cudaFuncAttributeMaxDynamicSharedMemorySize, SM_TOT_L);

    dim3 grid(16, 256);
    xproj_kernel<<<grid, 256, smem_xproj>>>(src, Wih, bih, bhh, lens);
    lstm_kernel<<<NCTA, 256, SM_TOT_L>>>(lens, Whh, out);
}